// round 16
// baseline (speedup 1.0000x reference)
#include <cuda_runtime.h>
#include <cuda_fp16.h>
#include <math.h>
#include <stdint.h>

#define BB 4
#define LL 2048
#define CC 1024
#define C3 3072

// Scratch (device globals are the sanctioned scratch mechanism)
__device__ __half g_qkvh[(size_t)BB * LL * C3];  // 48 MB qkv (fp16)
__device__ float  g_attn[(size_t)BB * LL * LL];  // 64 MB scores (fp32, exact)
__device__ __half g_ph[(size_t)BB * LL * LL];    // 32 MB softmax probs (fp16)
__device__ __half g_oh[(size_t)BB * LL * CC];    // 16 MB attention out (fp16)
__device__ __half g_vth[(size_t)BB * CC * LL];   // 16 MB V transposed, K-major (fp16)
__device__ __half g_xh[(size_t)BB * LL * CC];    // 16 MB x (fp16)
__device__ __half g_wqh[(size_t)C3 * CC];        //  6 MB w_qkv (fp16)
__device__ __half g_woh[(size_t)CC * CC];        //  2 MB w_out (fp16)

// ---------------- helpers ----------------
__device__ __forceinline__ uint32_t smem_u32(const void* p) {
    uint32_t a;
    asm("{ .reg .u64 t; cvta.to.shared.u64 t, %1; cvt.u32.u64 %0, t; }" : "=r"(a) : "l"(p));
    return a;
}
__device__ __forceinline__ uint32_t swz(uint32_t off) {  // 128B-row XOR swizzle
    return off ^ ((off >> 3) & 0x70);
}
__device__ __forceinline__ void ldsm4(uint32_t (&r)[4], uint32_t addr) {
    asm volatile("ldmatrix.sync.aligned.m8n8.x4.shared.b16 {%0,%1,%2,%3}, [%4];"
                 : "=r"(r[0]), "=r"(r[1]), "=r"(r[2]), "=r"(r[3]) : "r"(addr));
}
__device__ __forceinline__ void mma_f16(float (&d)[4], const uint32_t (&a)[4],
                                        const uint32_t b0, const uint32_t b1) {
    asm volatile("mma.sync.aligned.m16n8k16.row.col.f32.f16.f16.f32 "
                 "{%0,%1,%2,%3}, {%4,%5,%6,%7}, {%8,%9}, {%0,%1,%2,%3};"
                 : "+f"(d[0]), "+f"(d[1]), "+f"(d[2]), "+f"(d[3])
                 : "r"(a[0]), "r"(a[1]), "r"(a[2]), "r"(a[3]), "r"(b0), "r"(b1));
}
#define CPA16(dst, src) \
    asm volatile("cp.async.cg.shared.global [%0], [%1], 16;" :: "r"(dst), "l"(src) : "memory")
#define CPA_COMMIT() asm volatile("cp.async.commit_group;" ::: "memory")
template <int N>
__device__ __forceinline__ void cpa_wait() {
    asm volatile("cp.async.wait_group %0;" :: "n"(N) : "memory");
}

// Tile: 128 rows x 64 k-halfs = 128B rows, XOR-swizzled. Chunk = k64.
// Stage = A tile (16KB) + B tile (16KB). 3 stages = 96KB dynamic smem, 2 CTAs/SM.
#define TILE_BYTES  16384
#define STAGE_BYTES 32768
#define NSTAGE      3
#define SMEM_DYN    (NSTAGE * STAGE_BYTES)

// ---------------- fp16 mma.sync GEMM (both operands K-major, cp.async 3-stage) ----------------
// C[m0..+128, n0..+128] = scale * A(rows m0.., lda) . B(rows n0.., ldb)^T  (fp16 in, fp32 accum)
// Ksz multiple of 64, >= 128. MASK: causal -inf where col > row (fp32 out only).
// OUTH: store fp16 (for downstream GEMMs); else fp32.
template <bool MASK, bool OUTH>
__device__ __forceinline__ void tc_gemm(const __half* __restrict__ A, int lda,
                                        const __half* __restrict__ B, int ldb,
                                        void* __restrict__ Cv, int ldc,
                                        int Ksz, int m0, int n0, float scale)
{
    extern __shared__ __align__(128) char dsm[];
    const uint32_t sb = smem_u32(dsm);

    const int tid = threadIdx.x;
    const int ln = tid & 31, wid = tid >> 5;
    const int wm = wid >> 2, wn = wid & 3;     // warp tile origin (wm*64, wn*32)
    const int gid = ln >> 2, tig = ln & 3;

    // cp.async coords: 2 threads per 128B row; each thread does 4 consecutive 16B units
    const int rA = tid >> 1, cg0 = (tid & 1) * 4;

    // ldmatrix invariant pieces (16B unit = 8 halfs = one k8 half of a k16 step)
    const int rowAf = wm * 64 + (ln & 7) + ((ln >> 3) & 1) * 8;
    const int colA16 = ln >> 4;
    const int rowBf = wn * 32 + (ln & 7) + ((ln >> 4) & 1) * 8;
    const int colB16 = (ln >> 3) & 1;

    float acc[4][4][4];
#pragma unroll
    for (int i = 0; i < 4; i++)
#pragma unroll
        for (int j = 0; j < 4; j++)
#pragma unroll
            for (int e = 0; e < 4; e++) acc[i][j][e] = 0.f;

    const int nch = Ksz >> 6;   // k64 chunks (nch >= 2 at all call sites)

    // Issue 2 CPA16 (one A, one B 16B unit) for 16B-column group h of chunk kc into stage s.
    auto issue_part = [&](int kc, int s, int h) {
        const uint32_t st = sb + (uint32_t)(s * STAGE_BYTES);
        const int c16 = cg0 + h;
        const __half* gA = A + (size_t)(m0 + rA) * lda + kc * 64 + c16 * 8;
        const __half* gB = B + (size_t)(n0 + rA) * ldb + kc * 64 + c16 * 8;
        CPA16(st + swz((uint32_t)(rA * 128 + c16 * 16)), gA);
        CPA16(st + TILE_BYTES + swz((uint32_t)(rA * 128 + c16 * 16)), gB);
    };
    auto issue_chunk = [&](int kc, int s) {   // prologue only: all 8 at once
#pragma unroll
        for (int h = 0; h < 4; h++) issue_part(kc, s, h);
        CPA_COMMIT();
    };

    auto compute_k16 = [&](int s, int q) {   // q = k16 step within k64 chunk (0..3)
        const uint32_t aB = sb + (uint32_t)(s * STAGE_BYTES);
        const uint32_t bB = aB + TILE_BYTES;
        uint32_t af[4][4];
#pragma unroll
        for (int i = 0; i < 4; i++)
            ldsm4(af[i], aB + swz((uint32_t)((rowAf + i * 16) * 128 + q * 32 + colA16 * 16)));
        // Split B halves: MMAs start sooner, L1 pressure spread.
#pragma unroll
        for (int p = 0; p < 2; ++p) {
            uint32_t qq[4];
            ldsm4(qq, bB + swz((uint32_t)((rowBf + p * 16) * 128 + q * 32 + colB16 * 16)));
#pragma unroll
            for (int i = 0; i < 4; i++) {
                mma_f16(acc[i][2 * p],     af[i], qq[0], qq[1]);
                mma_f16(acc[i][2 * p + 1], af[i], qq[2], qq[3]);
            }
        }
    };

    // prologue: 2 chunks in flight
    issue_chunk(0, 0);
    issue_chunk(1, 1);

    int s = 0;
    for (int c = 0; c < nch; ++c) {
        cpa_wait<1>();          // chunk c's group complete (chunk c+1's may pend)
        __syncthreads();        // single barrier: visibility of chunk c AND proof all threads
                                // finished chunk c-1 -> stage (s+2)%3 safe to reissue
        const bool pre = (c + 2 < nch);
        int s2 = s + 2;
        if (s2 >= NSTAGE) s2 -= NSTAGE;
#pragma unroll
        for (int q = 0; q < 4; ++q) {      // interleave prefetch issue with compute steps
            if (pre) issue_part(c + 2, s2, q);
            compute_k16(s, q);             // round-12 order (rotation reverted: falsified)
        }
        CPA_COMMIT();           // exactly one group per iteration (empty in tail)
        if (++s == NSTAGE) s = 0;
    }

    // ---- epilogue ----
#pragma unroll
    for (int i = 0; i < 4; i++) {
        const int row0 = m0 + wm * 64 + i * 16 + gid;
#pragma unroll
        for (int j = 0; j < 4; j++) {
            const int col = n0 + wn * 32 + j * 8 + 2 * tig;
            float v00 = acc[i][j][0] * scale, v01 = acc[i][j][1] * scale;
            float v10 = acc[i][j][2] * scale, v11 = acc[i][j][3] * scale;
            if (MASK) {
                if (col > row0)         v00 = -INFINITY;
                if (col + 1 > row0)     v01 = -INFINITY;
                if (col > row0 + 8)     v10 = -INFINITY;
                if (col + 1 > row0 + 8) v11 = -INFINITY;
            }
            if (OUTH) {
                __half* C = (__half*)Cv;
                *(__half2*)(C + (size_t)row0 * ldc + col) = __floats2half2_rn(v00, v01);
                *(__half2*)(C + (size_t)(row0 + 8) * ldc + col) = __floats2half2_rn(v10, v11);
            } else {
                float* C = (float*)Cv;
                float2 a0; a0.x = v00; a0.y = v01;
                float2 a1; a1.x = v10; a1.y = v11;
                *(float2*)(C + (size_t)row0 * ldc + col) = a0;
                *(float2*)(C + (size_t)(row0 + 8) * ldc + col) = a1;
            }
        }
    }
}

// ---------------- small prep kernels ----------------
__global__ void __launch_bounds__(256) k_half(const float* __restrict__ in,
                                              __half* __restrict__ out, int n4) {
    int i = blockIdx.x * 256 + threadIdx.x;
    int stride = gridDim.x * 256;
    for (; i < n4; i += stride) {
        float4 v = ((const float4*)in)[i];
        ((__half2*)out)[2 * i]     = __floats2half2_rn(v.x, v.y);
        ((__half2*)out)[2 * i + 1] = __floats2half2_rn(v.z, v.w);
    }
}

// ---------------- stage kernels (256 threads, 2 CTAs/SM) ----------------
__global__ void __launch_bounds__(256, 2) k_qkv() {
    tc_gemm<false, true>(g_xh, CC, g_wqh, CC, g_qkvh, C3, CC,
                         blockIdx.y * 128, blockIdx.x * 128, 1.f);
}

// score GEMM; the 120/256 fully-masked tiles per batch instead perform the V transpose
// (g_qkvh V slice [b][l][2048+c] -> g_vth [b][c][l]), hiding it under the score launch.
__global__ void __launch_bounds__(256, 2) k_score() {
    const int b = blockIdx.z;
    const int bx = blockIdx.x, by = blockIdx.y;
    const int m0 = by * 128, n0 = bx * 128;
    const int tid = threadIdx.x;

    if (n0 > m0) {
        // Skipped-tile CTA: do transpose tiles. Linear index among skipped tiles of this batch:
        // row by contributes (15-by) skipped tiles (bx in by+1..15).
        const int si = by * 15 - (by * (by - 1)) / 2 + (bx - by - 1);   // 0..119
        __shared__ __half ttile[32][34];
        const int tx = tid & 31, ty = tid >> 5;                         // 32 x 8
        for (int t = si; t < 2048; t += 120) {                          // 32 c-tiles x 64 l-tiles
            const int c0 = (t & 31) * 32, l0 = (t >> 5) * 32;
#pragma unroll
            for (int i = 0; i < 4; i++) {
                int l = l0 + ty + i * 8;
                ttile[ty + i * 8][tx] = g_qkvh[((size_t)b * LL + l) * C3 + 2 * CC + c0 + tx];
            }
            __syncthreads();
#pragma unroll
            for (int i = 0; i < 4; i++) {
                int c = c0 + ty + i * 8;
                g_vth[((size_t)b * CC + c) * LL + l0 + tx] = ttile[tx][ty + i * 8];
            }
            __syncthreads();
        }
        return;
    }
    const __half* Q = g_qkvh + (size_t)b * LL * C3;
    tc_gemm<true, false>(Q, C3, Q + CC, C3, g_attn + (size_t)b * LL * LL, LL, CC,
                         m0, n0, 0.03125f);
}

__global__ void __launch_bounds__(256) softmax_kernel() {
    int q = blockIdx.x, b = blockIdx.y;
    const float4* row4 = (const float4*)(g_attn + ((size_t)b * LL + q) * LL);
    __half2* rowp2 = (__half2*)(g_ph + ((size_t)b * LL + q) * LL);
    int kend = ((q >> 7) + 1) << 7;           // multiple of 128
    int tid = threadIdx.x;

    float v[8];
#pragma unroll
    for (int p = 0; p < 2; p++) {
        int g = tid + p * 256;                // float4 group; elements 4g..4g+3
        if (4 * g < kend) {
            float4 t = row4[g];
            v[4 * p] = t.x; v[4 * p + 1] = t.y; v[4 * p + 2] = t.z; v[4 * p + 3] = t.w;
        } else {
            v[4 * p] = v[4 * p + 1] = v[4 * p + 2] = v[4 * p + 3] = -INFINITY;
        }
    }
    float m = -INFINITY;
#pragma unroll
    for (int i = 0; i < 8; i++) m = fmaxf(m, v[i]);

    __shared__ float sred[8];
#pragma unroll
    for (int o = 16; o; o >>= 1) m = fmaxf(m, __shfl_xor_sync(0xffffffffu, m, o));
    if ((tid & 31) == 0) sred[tid >> 5] = m;
    __syncthreads();
    if (tid < 32) {
        float x = (tid < 8) ? sred[tid] : -INFINITY;
#pragma unroll
        for (int o = 4; o; o >>= 1) x = fmaxf(x, __shfl_xor_sync(0xffffffffu, x, o));
        if (tid == 0) sred[0] = x;
    }
    __syncthreads();
    m = sred[0];
    __syncthreads();

    float s = 0.f;
#pragma unroll
    for (int i = 0; i < 8; i++) { v[i] = __expf(v[i] - m); s += v[i]; }
#pragma unroll
    for (int o = 16; o; o >>= 1) s += __shfl_xor_sync(0xffffffffu, s, o);
    if ((tid & 31) == 0) sred[tid >> 5] = s;
    __syncthreads();
    if (tid < 32) {
        float x = (tid < 8) ? sred[tid] : 0.f;
#pragma unroll
        for (int o = 4; o; o >>= 1) x += __shfl_xor_sync(0xffffffffu, x, o);
        if (tid == 0) sred[0] = x;
    }
    __syncthreads();
    float inv = 1.0f / sred[0];
#pragma unroll
    for (int p = 0; p < 2; p++) {
        int g = tid + p * 256;
        if (4 * g < kend) {
            rowp2[2 * g]     = __floats2half2_rn(v[4 * p] * inv, v[4 * p + 1] * inv);
            rowp2[2 * g + 1] = __floats2half2_rn(v[4 * p + 2] * inv, v[4 * p + 3] * inv);
        }
    }
}

__global__ void __launch_bounds__(256, 2) k_pv() {
    const int b = blockIdx.z;
    // longest-K tiles first (K = m0 + 128 grows with m0)
    const int by = gridDim.y - 1 - blockIdx.y;
    const int m0 = by * 128, n0 = blockIdx.x * 128;
    const __half* P = g_ph + (size_t)b * LL * LL;
    const __half* Vt = g_vth + (size_t)b * CC * LL;
    tc_gemm<false, true>(P, LL, Vt, LL, g_oh + (size_t)b * LL * CC, CC,
                         m0 + 128 /* causal K truncation; == kend of every row in tile */,
                         m0, n0, 1.f);
}

__global__ void __launch_bounds__(256, 2) k_out(float* __restrict__ y) {
    tc_gemm<false, false>(g_oh, CC, g_woh, CC, y, CC, CC,
                          blockIdx.y * 128, blockIdx.x * 128, 1.f);
}

extern "C" void kernel_launch(void* const* d_in, const int* in_sizes, int n_in,
                              void* d_out, int out_size)
{
    const float* x     = (const float*)d_in[0];
    const float* w_qkv = (const float*)d_in[1];
    const float* w_out = (const float*)d_in[2];
    float* y = (float*)d_out;

    static int configured = 0;
    if (!configured) {
        cudaFuncSetAttribute(k_qkv,   cudaFuncAttributeMaxDynamicSharedMemorySize, SMEM_DYN);
        cudaFuncSetAttribute(k_score, cudaFuncAttributeMaxDynamicSharedMemorySize, SMEM_DYN);
        cudaFuncSetAttribute(k_pv,    cudaFuncAttributeMaxDynamicSharedMemorySize, SMEM_DYN);
        cudaFuncSetAttribute(k_out,   cudaFuncAttributeMaxDynamicSharedMemorySize, SMEM_DYN);
        configured = 1;
    }

    __half* gx;  cudaGetSymbolAddress((void**)&gx,  g_xh);
    __half* gwq; cudaGetSymbolAddress((void**)&gwq, g_wqh);
    __half* gwo; cudaGetSymbolAddress((void**)&gwo, g_woh);

    k_half<<<512, 256>>>(x,     gx,  (BB * LL * CC) / 4);
    k_half<<<512, 256>>>(w_qkv, gwq, (C3 * CC) / 4);
    k_half<<<256, 256>>>(w_out, gwo, (CC * CC) / 4);

    k_qkv<<<dim3(C3 / 128, (BB * LL) / 128), 256, SMEM_DYN>>>();
    k_score<<<dim3(LL / 128, LL / 128, BB), 256, SMEM_DYN>>>();  // masked tiles do V transpose
    softmax_kernel<<<dim3(LL, BB), 256>>>();
    k_pv<<<dim3(CC / 128, LL / 128, BB), 256, SMEM_DYN>>>();
    k_out<<<dim3(CC / 128, (BB * LL) / 128), 256, SMEM_DYN>>>(y);
}

// round 17
// speedup vs baseline: 1.0455x; 1.0455x over previous
#include <cuda_runtime.h>
#include <cuda_fp16.h>
#include <math.h>
#include <stdint.h>

#define BB 4
#define LL 2048
#define CC 1024
#define C3 3072

// Scratch (device globals are the sanctioned scratch mechanism)
__device__ __half g_qkvh[(size_t)BB * LL * C3];  // 48 MB qkv (fp16)
__device__ float  g_attn[(size_t)BB * LL * LL];  // 64 MB scores (fp32, exact)
__device__ __half g_ph[(size_t)BB * LL * LL];    // 32 MB softmax probs (fp16)
__device__ __half g_oh[(size_t)BB * LL * CC];    // 16 MB attention out (fp16)
__device__ __half g_vth[(size_t)BB * CC * LL];   // 16 MB V transposed, K-major (fp16)
__device__ __half g_xh[(size_t)BB * LL * CC];    // 16 MB x (fp16)
__device__ __half g_wqh[(size_t)C3 * CC];        //  6 MB w_qkv (fp16)
__device__ __half g_woh[(size_t)CC * CC];        //  2 MB w_out (fp16)

// ---------------- helpers ----------------
__device__ __forceinline__ uint32_t smem_u32(const void* p) {
    uint32_t a;
    asm("{ .reg .u64 t; cvta.to.shared.u64 t, %1; cvt.u32.u64 %0, t; }" : "=r"(a) : "l"(p));
    return a;
}
__device__ __forceinline__ uint32_t swz(uint32_t off) {  // 128B-row XOR swizzle
    return off ^ ((off >> 3) & 0x70);
}
__device__ __forceinline__ void ldsm4(uint32_t (&r)[4], uint32_t addr) {
    asm volatile("ldmatrix.sync.aligned.m8n8.x4.shared.b16 {%0,%1,%2,%3}, [%4];"
                 : "=r"(r[0]), "=r"(r[1]), "=r"(r[2]), "=r"(r[3]) : "r"(addr));
}
__device__ __forceinline__ void mma_f16(float (&d)[4], const uint32_t (&a)[4],
                                        const uint32_t b0, const uint32_t b1) {
    asm volatile("mma.sync.aligned.m16n8k16.row.col.f32.f16.f16.f32 "
                 "{%0,%1,%2,%3}, {%4,%5,%6,%7}, {%8,%9}, {%0,%1,%2,%3};"
                 : "+f"(d[0]), "+f"(d[1]), "+f"(d[2]), "+f"(d[3])
                 : "r"(a[0]), "r"(a[1]), "r"(a[2]), "r"(a[3]), "r"(b0), "r"(b1));
}
#define CPA16(dst, src) \
    asm volatile("cp.async.cg.shared.global [%0], [%1], 16;" :: "r"(dst), "l"(src) : "memory")
#define CPA_COMMIT() asm volatile("cp.async.commit_group;" ::: "memory")
template <int N>
__device__ __forceinline__ void cpa_wait() {
    asm volatile("cp.async.wait_group %0;" :: "n"(N) : "memory");
}

// Tile: 128 rows x 64 k-halfs = 128B rows, XOR-swizzled. Chunk = k64.
// Stage = A tile (16KB) + B tile (16KB). 3 stages = 96KB dynamic smem, 2 CTAs/SM.
#define TILE_BYTES  16384
#define STAGE_BYTES 32768
#define NSTAGE      3
#define SMEM_DYN    (NSTAGE * STAGE_BYTES)

// ---------------- fp16 mma.sync GEMM (both operands K-major, cp.async 3-stage) ----------------
// C[m0..+128, n0..+128] = scale * A(rows m0.., lda) . B(rows n0.., ldb)^T  (fp16 in, fp32 accum)
// Ksz multiple of 64, >= 128. MASK: causal -inf where col > row (fp32 out only).
// OUTH: store fp16 (for downstream GEMMs); else fp32.
template <bool MASK, bool OUTH>
__device__ __forceinline__ void tc_gemm(const __half* __restrict__ A, int lda,
                                        const __half* __restrict__ B, int ldb,
                                        void* __restrict__ Cv, int ldc,
                                        int Ksz, int m0, int n0, float scale)
{
    extern __shared__ __align__(128) char dsm[];
    const uint32_t sb = smem_u32(dsm);

    const int tid = threadIdx.x;
    const int ln = tid & 31, wid = tid >> 5;
    const int wm = wid >> 2, wn = wid & 3;     // warp tile origin (wm*64, wn*32)
    const int gid = ln >> 2, tig = ln & 3;

    // cp.async coords: 2 threads per 128B row; each thread does 4 consecutive 16B units
    const int rA = tid >> 1, cg0 = (tid & 1) * 4;

    // ldmatrix invariant pieces (16B unit = 8 halfs = one k8 half of a k16 step)
    const int rowAf = wm * 64 + (ln & 7) + ((ln >> 3) & 1) * 8;
    const int colA16 = ln >> 4;
    const int rowBf = wn * 32 + (ln & 7) + ((ln >> 4) & 1) * 8;
    const int colB16 = (ln >> 3) & 1;

    float acc[4][4][4];
#pragma unroll
    for (int i = 0; i < 4; i++)
#pragma unroll
        for (int j = 0; j < 4; j++)
#pragma unroll
            for (int e = 0; e < 4; e++) acc[i][j][e] = 0.f;

    const int nch = Ksz >> 6;   // k64 chunks (nch >= 2 at all call sites)

    // Issue 2 CPA16 (one A, one B 16B unit) for 16B-column group h of chunk kc into stage s.
    auto issue_part = [&](int kc, int s, int h) {
        const uint32_t st = sb + (uint32_t)(s * STAGE_BYTES);
        const int c16 = cg0 + h;
        const __half* gA = A + (size_t)(m0 + rA) * lda + kc * 64 + c16 * 8;
        const __half* gB = B + (size_t)(n0 + rA) * ldb + kc * 64 + c16 * 8;
        CPA16(st + swz((uint32_t)(rA * 128 + c16 * 16)), gA);
        CPA16(st + TILE_BYTES + swz((uint32_t)(rA * 128 + c16 * 16)), gB);
    };
    auto issue_chunk = [&](int kc, int s) {   // prologue only: all 8 at once
#pragma unroll
        for (int h = 0; h < 4; h++) issue_part(kc, s, h);
        CPA_COMMIT();
    };

    auto compute_k16 = [&](int s, int q) {   // q = k16 step within k64 chunk (0..3)
        const uint32_t aB = sb + (uint32_t)(s * STAGE_BYTES);
        const uint32_t bB = aB + TILE_BYTES;
        uint32_t af[4][4];
#pragma unroll
        for (int i = 0; i < 4; i++)
            ldsm4(af[i], aB + swz((uint32_t)((rowAf + i * 16) * 128 + q * 32 + colA16 * 16)));
        // Split B halves: MMAs start sooner, L1 pressure spread.
#pragma unroll
        for (int p = 0; p < 2; ++p) {
            uint32_t qq[4];
            ldsm4(qq, bB + swz((uint32_t)((rowBf + p * 16) * 128 + q * 32 + colB16 * 16)));
#pragma unroll
            for (int i = 0; i < 4; i++) {
                mma_f16(acc[i][2 * p],     af[i], qq[0], qq[1]);
                mma_f16(acc[i][2 * p + 1], af[i], qq[2], qq[3]);
            }
        }
    };

    // prologue: 2 chunks in flight
    issue_chunk(0, 0);
    issue_chunk(1, 1);

    int s = 0;
    for (int c = 0; c < nch; ++c) {
        cpa_wait<1>();          // chunk c's group complete (chunk c+1's may pend)
        __syncthreads();        // single barrier: visibility of chunk c AND proof all threads
                                // finished chunk c-1 -> stage (s+2)%3 safe to reissue
        const bool pre = (c + 2 < nch);
        int s2 = s + 2;
        if (s2 >= NSTAGE) s2 -= NSTAGE;
#pragma unroll
        for (int q = 0; q < 4; ++q) {      // interleave prefetch issue with compute steps
            if (pre) issue_part(c + 2, s2, q);
            compute_k16(s, q);
        }
        CPA_COMMIT();           // exactly one group per iteration (empty in tail)
        if (++s == NSTAGE) s = 0;
    }

    // ---- epilogue ----
#pragma unroll
    for (int i = 0; i < 4; i++) {
        const int row0 = m0 + wm * 64 + i * 16 + gid;
#pragma unroll
        for (int j = 0; j < 4; j++) {
            const int col = n0 + wn * 32 + j * 8 + 2 * tig;
            float v00 = acc[i][j][0] * scale, v01 = acc[i][j][1] * scale;
            float v10 = acc[i][j][2] * scale, v11 = acc[i][j][3] * scale;
            if (MASK) {
                if (col > row0)         v00 = -INFINITY;
                if (col + 1 > row0)     v01 = -INFINITY;
                if (col > row0 + 8)     v10 = -INFINITY;
                if (col + 1 > row0 + 8) v11 = -INFINITY;
            }
            if (OUTH) {
                __half* C = (__half*)Cv;
                *(__half2*)(C + (size_t)row0 * ldc + col) = __floats2half2_rn(v00, v01);
                *(__half2*)(C + (size_t)(row0 + 8) * ldc + col) = __floats2half2_rn(v10, v11);
            } else {
                float* C = (float*)Cv;
                float2 a0; a0.x = v00; a0.y = v01;
                float2 a1; a1.x = v10; a1.y = v11;
                *(float2*)(C + (size_t)row0 * ldc + col) = a0;
                *(float2*)(C + (size_t)(row0 + 8) * ldc + col) = a1;
            }
        }
    }
}

// ---------------- prep: one launch converts all three fp32 inputs to fp16 ----------------
__global__ void __launch_bounds__(256) k_half3(const float* __restrict__ x,
                                               const float* __restrict__ wq,
                                               const float* __restrict__ wo,
                                               __half* __restrict__ xh,
                                               __half* __restrict__ wqh,
                                               __half* __restrict__ woh) {
    const float* in;
    __half* out;
    int n4;
    if (blockIdx.y == 0)      { in = x;  out = xh;  n4 = (BB * LL * CC) / 4; }
    else if (blockIdx.y == 1) { in = wq; out = wqh; n4 = (C3 * CC) / 4; }
    else                      { in = wo; out = woh; n4 = (CC * CC) / 4; }
    int i = blockIdx.x * 256 + threadIdx.x;
    int stride = gridDim.x * 256;
    for (; i < n4; i += stride) {
        float4 v = ((const float4*)in)[i];
        ((__half2*)out)[2 * i]     = __floats2half2_rn(v.x, v.y);
        ((__half2*)out)[2 * i + 1] = __floats2half2_rn(v.z, v.w);
    }
}

// V slice of g_qkvh [b][l][2048+c] -> g_vth [b][c][l]  (standalone: fully parallel, ~8us)
__global__ void __launch_bounds__(256) k_transpose_v() {
    __shared__ __half tile[32][34];
    const int b = blockIdx.z;
    const int c0 = blockIdx.x * 32, l0 = blockIdx.y * 32;
    const int tx = threadIdx.x, ty = threadIdx.y;
#pragma unroll
    for (int i = 0; i < 4; i++) {
        int l = l0 + ty + i * 8;
        tile[ty + i * 8][tx] = g_qkvh[((size_t)b * LL + l) * C3 + 2 * CC + c0 + tx];
    }
    __syncthreads();
#pragma unroll
    for (int i = 0; i < 4; i++) {
        int c = c0 + ty + i * 8;
        g_vth[((size_t)b * CC + c) * LL + l0 + tx] = tile[tx][ty + i * 8];
    }
}

// ---------------- stage kernels (256 threads, 2 CTAs/SM) ----------------
__global__ void __launch_bounds__(256, 2) k_qkv() {
    tc_gemm<false, true>(g_xh, CC, g_wqh, CC, g_qkvh, C3, CC,
                         blockIdx.y * 128, blockIdx.x * 128, 1.f);
}

__global__ void __launch_bounds__(256, 2) k_score() {
    const int b = blockIdx.z;
    const int m0 = blockIdx.y * 128, n0 = blockIdx.x * 128;
    if (n0 > m0) return;  // fully-masked block: never read by softmax
    const __half* Q = g_qkvh + (size_t)b * LL * C3;
    tc_gemm<true, false>(Q, C3, Q + CC, C3, g_attn + (size_t)b * LL * LL, LL, CC,
                         m0, n0, 0.03125f);
}

__global__ void __launch_bounds__(256) softmax_kernel() {
    int q = blockIdx.x, b = blockIdx.y;
    const float4* row4 = (const float4*)(g_attn + ((size_t)b * LL + q) * LL);
    __half2* rowp2 = (__half2*)(g_ph + ((size_t)b * LL + q) * LL);
    int kend = ((q >> 7) + 1) << 7;           // multiple of 128
    int tid = threadIdx.x;

    float v[8];
#pragma unroll
    for (int p = 0; p < 2; p++) {
        int g = tid + p * 256;                // float4 group; elements 4g..4g+3
        if (4 * g < kend) {
            float4 t = row4[g];
            v[4 * p] = t.x; v[4 * p + 1] = t.y; v[4 * p + 2] = t.z; v[4 * p + 3] = t.w;
        } else {
            v[4 * p] = v[4 * p + 1] = v[4 * p + 2] = v[4 * p + 3] = -INFINITY;
        }
    }
    float m = -INFINITY;
#pragma unroll
    for (int i = 0; i < 8; i++) m = fmaxf(m, v[i]);

    __shared__ float sred[8];
#pragma unroll
    for (int o = 16; o; o >>= 1) m = fmaxf(m, __shfl_xor_sync(0xffffffffu, m, o));
    if ((tid & 31) == 0) sred[tid >> 5] = m;
    __syncthreads();
    if (tid < 32) {
        float x = (tid < 8) ? sred[tid] : -INFINITY;
#pragma unroll
        for (int o = 4; o; o >>= 1) x = fmaxf(x, __shfl_xor_sync(0xffffffffu, x, o));
        if (tid == 0) sred[0] = x;
    }
    __syncthreads();
    m = sred[0];
    __syncthreads();

    float s = 0.f;
#pragma unroll
    for (int i = 0; i < 8; i++) { v[i] = __expf(v[i] - m); s += v[i]; }
#pragma unroll
    for (int o = 16; o; o >>= 1) s += __shfl_xor_sync(0xffffffffu, s, o);
    if ((tid & 31) == 0) sred[tid >> 5] = s;
    __syncthreads();
    if (tid < 32) {
        float x = (tid < 8) ? sred[tid] : 0.f;
#pragma unroll
        for (int o = 4; o; o >>= 1) x += __shfl_xor_sync(0xffffffffu, x, o);
        if (tid == 0) sred[0] = x;
    }
    __syncthreads();
    float inv = 1.0f / sred[0];
#pragma unroll
    for (int p = 0; p < 2; p++) {
        int g = tid + p * 256;
        if (4 * g < kend) {
            rowp2[2 * g]     = __floats2half2_rn(v[4 * p] * inv, v[4 * p + 1] * inv);
            rowp2[2 * g + 1] = __floats2half2_rn(v[4 * p + 2] * inv, v[4 * p + 3] * inv);
        }
    }
}

__global__ void __launch_bounds__(256, 2) k_pv() {
    const int b = blockIdx.z;
    // longest-K tiles first (K = m0 + 128 grows with m0)
    const int by = gridDim.y - 1 - blockIdx.y;
    const int m0 = by * 128, n0 = blockIdx.x * 128;
    const __half* P = g_ph + (size_t)b * LL * LL;
    const __half* Vt = g_vth + (size_t)b * CC * LL;
    tc_gemm<false, true>(P, LL, Vt, LL, g_oh + (size_t)b * LL * CC, CC,
                         m0 + 128 /* causal K truncation; == kend of every row in tile */,
                         m0, n0, 1.f);
}

__global__ void __launch_bounds__(256, 2) k_out(float* __restrict__ y) {
    tc_gemm<false, false>(g_oh, CC, g_woh, CC, y, CC, CC,
                          blockIdx.y * 128, blockIdx.x * 128, 1.f);
}

extern "C" void kernel_launch(void* const* d_in, const int* in_sizes, int n_in,
                              void* d_out, int out_size)
{
    const float* x     = (const float*)d_in[0];
    const float* w_qkv = (const float*)d_in[1];
    const float* w_out = (const float*)d_in[2];
    float* y = (float*)d_out;

    static int configured = 0;
    if (!configured) {
        cudaFuncSetAttribute(k_qkv,   cudaFuncAttributeMaxDynamicSharedMemorySize, SMEM_DYN);
        cudaFuncSetAttribute(k_score, cudaFuncAttributeMaxDynamicSharedMemorySize, SMEM_DYN);
        cudaFuncSetAttribute(k_pv,    cudaFuncAttributeMaxDynamicSharedMemorySize, SMEM_DYN);
        cudaFuncSetAttribute(k_out,   cudaFuncAttributeMaxDynamicSharedMemorySize, SMEM_DYN);
        configured = 1;
    }

    __half* gx;  cudaGetSymbolAddress((void**)&gx,  g_xh);
    __half* gwq; cudaGetSymbolAddress((void**)&gwq, g_wqh);
    __half* gwo; cudaGetSymbolAddress((void**)&gwo, g_woh);

    k_half3<<<dim3(296, 3), 256>>>(x, w_qkv, w_out, gx, gwq, gwo);

    k_qkv<<<dim3(C3 / 128, (BB * LL) / 128), 256, SMEM_DYN>>>();
    k_transpose_v<<<dim3(CC / 32, LL / 32, BB), dim3(32, 8)>>>();
    k_score<<<dim3(LL / 128, LL / 128, BB), 256, SMEM_DYN>>>();
    softmax_kernel<<<dim3(LL, BB), 256>>>();
    k_pv<<<dim3(CC / 128, LL / 128, BB), 256, SMEM_DYN>>>();
    k_out<<<dim3(CC / 128, (BB * LL) / 128), 256, SMEM_DYN>>>(y);
}